// round 15
// baseline (speedup 1.0000x reference)
#include <cuda_runtime.h>
#include <cuda_fp16.h>
#include <cstdint>
#include <math.h>

// ---------------- scratch (device globals; no allocations allowed) ----------
#define NMAX 50000
#define NPAD 50048                           // 782 tiles * 64 rows
__device__ __half g_xh [(size_t)NMAX * 128]; // xh output, fp16
__device__ __half g_xin[(size_t)NPAD * 128]; // x input, fp16 (tail zero)
__device__ __half g_wh [128 * 128];          // W fp16, natural [k][n]
__device__ float  g_s  [NMAX * 4];           // (si0, si1, sj0, sj1) per node
__device__ double g_wd [NMAX];               // packed: deg*2^20 + sum(alpha0)

// ---------------- PTX helpers (base sm_103 target) --------------------------
__device__ __forceinline__ uint32_t smem_u32(const void* p) {
    uint32_t a;
    asm("{ .reg .u64 t; cvta.to.shared.u64 t, %1; cvt.u32.u64 %0, t; }"
        : "=r"(a) : "l"(p));
    return a;
}
__device__ __forceinline__ void ldsm_x4(uint32_t& r0, uint32_t& r1,
                                        uint32_t& r2, uint32_t& r3, uint32_t addr) {
    asm volatile("ldmatrix.sync.aligned.m8n8.x4.shared.b16 {%0,%1,%2,%3}, [%4];"
                 : "=r"(r0), "=r"(r1), "=r"(r2), "=r"(r3) : "r"(addr));
}
__device__ __forceinline__ void ldsm_x4t(uint32_t& r0, uint32_t& r1,
                                         uint32_t& r2, uint32_t& r3, uint32_t addr) {
    asm volatile("ldmatrix.sync.aligned.m8n8.x4.trans.shared.b16 {%0,%1,%2,%3}, [%4];"
                 : "=r"(r0), "=r"(r1), "=r"(r2), "=r"(r3) : "r"(addr));
}
__device__ __forceinline__ void mma16816h(float* c, const uint32_t* a, const uint32_t* b) {
    asm volatile(
        "mma.sync.aligned.m16n8k16.row.col.f32.f16.f16.f32 "
        "{%0,%1,%2,%3}, {%4,%5,%6,%7}, {%8,%9}, {%0,%1,%2,%3};"
        : "+f"(c[0]), "+f"(c[1]), "+f"(c[2]), "+f"(c[3])
        : "r"(a[0]), "r"(a[1]), "r"(a[2]), "r"(a[3]), "r"(b[0]), "r"(b[1]));
}
__device__ __forceinline__ void cpa16(uint32_t dst, const void* src) {
    asm volatile("cp.async.cg.shared.global [%0], [%1], 16;" :: "r"(dst), "l"(src));
}
__device__ __forceinline__ void cpa_commit() {
    asm volatile("cp.async.commit_group;");
}
__device__ __forceinline__ void cpa_wait0() {
    asm volatile("cp.async.wait_group 0;" ::: "memory");
}

__device__ __forceinline__ uint32_t packh2(__half a, __half b) {
    return (uint32_t)__half_as_ushort(a) | ((uint32_t)__half_as_ushort(b) << 16);
}
__device__ __forceinline__ uint2 cvt4h(float4 v) {
    uint2 r;
    r.x = packh2(__float2half_rn(v.x), __float2half_rn(v.y));
    r.y = packh2(__float2half_rn(v.z), __float2half_rn(v.w));
    return r;
}

// ---------------- SMEM layout (bytes) ----------------------------------------
#define KP 136
#define O_ATT   0                       // 256 floats (ai|aj) = 1024B
#define O_PSI   1024                    // 1024B
#define O_PSJ   2048                    // 1024B
#define O_A0    3072                    // A buf0 [64 m][KP k] fp16 = 17408B
#define O_A1    (O_A0 + 17408)
#define O_B     (O_A1 + 17408)          // B [128 k][KP n] fp16 = 34816B
#define SMEM_TOTAL (O_B + 34816)        // 72704 -> 3 CTAs/SM

// ---------------- Kernel 0: prep — W->fp16, x->fp16, emb score terms ---------
#define PREP_WBLK 16
#define PREP_XBLK 1564                  // 1601536 float4s / (256*4)
__global__ void prep_kernel(const float* __restrict__ x, const float* __restrict__ W,
                            const float* __restrict__ emb,
                            const float* __restrict__ aei, const float* __restrict__ aej,
                            int N)
{
    int b = blockIdx.x, tid = threadIdx.x;
    if (b < PREP_WBLK) {                       // W convert: 4096 float4s
        int i = b * 256 + tid;
        ((uint2*)g_wh)[i] = cvt4h(((const float4*)W)[i]);
    } else if (b < PREP_WBLK + PREP_XBLK) {    // x convert (+ zero tail)
        int base = (b - PREP_WBLK) * 1024 + tid;
        const int nx4 = N * 32;                // 1600000 source float4s
#pragma unroll
        for (int i = 0; i < 4; i++) {
            int idx = base + i * 256;
            if (idx < NPAD * 32) {
                float4 v = (idx < nx4) ? ((const float4*)x)[idx]
                                       : make_float4(0.f, 0.f, 0.f, 0.f);
                ((uint2*)g_xin)[idx] = cvt4h(v);
            }
        }
    } else {                                   // emb score terms: warp per node
        int n = (b - PREP_WBLK - PREP_XBLK) * 8 + (tid >> 5);
        int lane = tid & 31;
        if (n >= N) return;
        float e0 = emb[(size_t)n * 64 + lane];
        float e1 = emb[(size_t)n * 64 + lane + 32];
        float ei0 = e0 * __ldg(aei + lane)      + e1 * __ldg(aei + lane + 32);
        float ei1 = e0 * __ldg(aei + 64 + lane) + e1 * __ldg(aei + 96 + lane);
        float ej0 = e0 * __ldg(aej + lane)      + e1 * __ldg(aej + lane + 32);
        float ej1 = e0 * __ldg(aej + 64 + lane) + e1 * __ldg(aej + 96 + lane);
#pragma unroll
        for (int o = 16; o > 0; o >>= 1) {
            ei0 += __shfl_xor_sync(0xffffffffu, ei0, o);
            ei1 += __shfl_xor_sync(0xffffffffu, ei1, o);
            ej0 += __shfl_xor_sync(0xffffffffu, ej0, o);
            ej1 += __shfl_xor_sync(0xffffffffu, ej1, o);
        }
        if (lane == 0) {
            *(float4*)(g_s + 4 * n) = make_float4(ei0, ei1, ej0, ej1);
            g_wd[n] = 0.0;
        }
    }
}

// ---------------- Kernel 1: persistent GEMM + scores (cp.async pipelined) ----
__global__ __launch_bounds__(256, 3)
void fused_gemm_kernel(const float* __restrict__ ai, const float* __restrict__ aj,
                       int N, int ntiles)
{
    extern __shared__ char sm[];
    const uint32_t smb = smem_u32(sm);
    const int tid = threadIdx.x;
    const int wid = tid >> 5;
    const int lid = tid & 31;

    // issue cp.async for first tile's A immediately (overlaps B staging)
    const uint32_t abuf[2] = { smb + O_A0, smb + O_A1 };
    {
        int row0 = blockIdx.x * 64;
#pragma unroll
        for (int i = 0; i < 4; i++) {
            int idx = tid + i * 256;
            int r = idx >> 4, c = (idx & 15) * 8;
            cpa16(abuf[0] + (uint32_t)(r * KP + c) * 2,
                  g_xin + (size_t)(row0 + r) * 128 + c);
        }
        cpa_commit();
    }

    // ---- stage B: pure uint4 copy of precomputed fp16 W -----------------------
#pragma unroll
    for (int i = 0; i < 8; i++) {
        int idx = tid + i * 256;
        int k = idx >> 4, n = (idx & 15) * 8;
        *(uint4*)(sm + O_B + (uint32_t)(k * KP + n) * 2) = ((const uint4*)g_wh)[idx];
    }
    // ---- stage attention vectors (ai | aj) -------------------------------------
    if (tid < 256) {
        float* satt = (float*)(sm + O_ATT);
        satt[tid] = (tid < 128) ? ai[tid] : aj[tid - 128];
    }

    // warp tile coords
    const int mrow = (wid & 1) * 32;
    const int ncol = (wid >> 1) * 32;
    const int q    = ncol >> 6;
    const int cg   = (ncol >> 5) & 1;
    const int g    = lid >> 2, tig = lid & 3;

    const int l15 = lid & 15;
    const int lh8 = (lid >> 4) * 8;
    const uint32_t aoff = (uint32_t)((mrow + l15) * KP + lh8) * 2;
    const int bkr = ((lid >> 3) & 1) * 8 + (lid & 7);
    const int bnc = (lid >> 4) * 8;
    const uint32_t boff = (uint32_t)(bkr * KP + ncol + bnc) * 2;

    const float* satt = (const float*)(sm + O_ATT);
    const float* attiq = satt + q * 64 + cg * 32;
    const float* attjq = satt + 128 + q * 64 + cg * 32;
    float* psiA = (float*)(sm + O_PSI);
    float* psjA = (float*)(sm + O_PSJ);

    int ibuf = 0;
    for (int tile = blockIdx.x; tile < ntiles; tile += gridDim.x, ibuf ^= 1) {
        const int row0 = tile * 64;

        cpa_wait0();
        __syncthreads();       // A(buf ibuf) visible; B/ATT staged; psi arrays free

        // issue next tile's A into the other buffer (hidden behind MMA+epilogue)
        {
            int nt = tile + gridDim.x;
            if (nt < ntiles) {
                int nrow0 = nt * 64;
#pragma unroll
                for (int i = 0; i < 4; i++) {
                    int idx = tid + i * 256;
                    int r = idx >> 4, c = (idx & 15) * 8;
                    cpa16(abuf[ibuf ^ 1] + (uint32_t)(r * KP + c) * 2,
                          g_xin + (size_t)(nrow0 + r) * 128 + c);
                }
            }
            cpa_commit();
        }

        // ---- MMA: single pass x 8 K-steps ----------------------------------------
        float acc[2][4][4];
#pragma unroll
        for (int t = 0; t < 2; t++)
#pragma unroll
            for (int n = 0; n < 4; n++)
#pragma unroll
                for (int k = 0; k < 4; k++) acc[t][n][k] = 0.f;

        const uint32_t abase = abuf[ibuf];
#pragma unroll
        for (int ks = 0; ks < 8; ks++) {
            const uint32_t akb = (uint32_t)ks * 32;
            const uint32_t bkb = (uint32_t)ks * (16 * KP * 2);
            uint32_t ah[2][4], b[4][2];
#pragma unroll
            for (int t = 0; t < 2; t++)
                ldsm_x4(ah[t][0], ah[t][1], ah[t][2], ah[t][3],
                        abase + aoff + (uint32_t)t * (16 * KP * 2) + akb);
#pragma unroll
            for (int p = 0; p < 2; p++)
                ldsm_x4t(b[2 * p][0], b[2 * p][1], b[2 * p + 1][0], b[2 * p + 1][1],
                         smb + O_B + boff + bkb + (uint32_t)p * 32);
#pragma unroll
            for (int t = 0; t < 2; t++)
#pragma unroll
                for (int n = 0; n < 4; n++) mma16816h(acc[t][n], ah[t], b[n]);
        }

        // ---- writeout of xh fragments as fp16 ------------------------------------
#pragma unroll
        for (int t = 0; t < 2; t++)
#pragma unroll
            for (int n = 0; n < 4; n++) {
                int r = row0 + mrow + t * 16 + g;
                int c = ncol + n * 8 + tig * 2;
                if (r < N)
                    *(uint32_t*)(g_xh + (size_t)r * 128 + c) =
                        packh2(__float2half_rn(acc[t][n][0]), __float2half_rn(acc[t][n][1]));
                if (r + 8 < N)
                    *(uint32_t*)(g_xh + (size_t)(r + 8) * 128 + c) =
                        packh2(__float2half_rn(acc[t][n][2]), __float2half_rn(acc[t][n][3]));
            }

        // ---- partial scores (register-only + satt) --------------------------------
        float psi[4], psj[4];
#pragma unroll
        for (int t = 0; t < 2; t++)
#pragma unroll
            for (int h = 0; h < 2; h++) {
                float si = 0.f, sj = 0.f;
#pragma unroll
                for (int n = 0; n < 4; n++) {
                    int c = n * 8 + tig * 2;
                    float v0 = acc[t][n][h * 2 + 0];
                    float v1 = acc[t][n][h * 2 + 1];
                    si += v0 * attiq[c] + v1 * attiq[c + 1];
                    sj += v0 * attjq[c] + v1 * attjq[c + 1];
                }
                psi[t * 2 + h] = si;
                psj[t * 2 + h] = sj;
            }
#pragma unroll
        for (int r = 0; r < 4; r++) {
            psi[r] += __shfl_xor_sync(0xffffffffu, psi[r], 1);
            psi[r] += __shfl_xor_sync(0xffffffffu, psi[r], 2);
            psj[r] += __shfl_xor_sync(0xffffffffu, psj[r], 1);
            psj[r] += __shfl_xor_sync(0xffffffffu, psj[r], 2);
        }
        if (tig == 0) {
#pragma unroll
            for (int t = 0; t < 2; t++)
#pragma unroll
                for (int h = 0; h < 2; h++) {
                    int lrow = mrow + t * 16 + h * 8 + g;
                    psiA[(q * 2 + cg) * 64 + lrow] = psi[t * 2 + h];
                    psjA[(q * 2 + cg) * 64 + lrow] = psj[t * 2 + h];
                }
        }
        __syncthreads();

        // ---- combine partials, ADD to emb terms already in g_s --------------------
        if (tid < 64) {
            int grow = row0 + tid;
            if (grow < N) {
                float4 s = *(float4*)(g_s + 4 * grow);
                s.x += psiA[tid]       + psiA[64 + tid];
                s.y += psiA[128 + tid] + psiA[192 + tid];
                s.z += psjA[tid]       + psjA[64 + tid];
                s.w += psjA[128 + tid] + psjA[192 + tid];
                *(float4*)(g_s + 4 * grow) = s;
            }
        }
    }
}

// ---------------- Kernel 2: per-edge attention, 4 edges/thread ---------------
__device__ __forceinline__ float edge_alpha0(float2 si, float2 sj) {
    float a0 = si.x + sj.x;  a0 = fmaxf(a0, 0.2f * a0);
    float a1 = si.y + sj.y;  a1 = fmaxf(a1, 0.2f * a1);
    return __fdividef(1.0f, 1.0f + __expf(a1 - a0));   // = e0/(e0+e1)
}

__global__ void edge_kernel(const int* __restrict__ src, const int* __restrict__ dst,
                            int Eq)
{
    int i = blockIdx.x * blockDim.x + threadIdx.x;
    if (i >= Eq) return;
    int4 s4 = ((const int4*)src)[i];
    int4 d4 = ((const int4*)dst)[i];

    float2 si_a = *(const float2*)(g_s + 4 * s4.x);
    float2 sj_a = *(const float2*)(g_s + 4 * d4.x + 2);
    float2 si_b = *(const float2*)(g_s + 4 * s4.y);
    float2 sj_b = *(const float2*)(g_s + 4 * d4.y + 2);
    float2 si_c = *(const float2*)(g_s + 4 * s4.z);
    float2 sj_c = *(const float2*)(g_s + 4 * d4.z + 2);
    float2 si_d = *(const float2*)(g_s + 4 * s4.w);
    float2 sj_d = *(const float2*)(g_s + 4 * d4.w + 2);

    float aa = edge_alpha0(si_a, sj_a);
    float ab = edge_alpha0(si_b, sj_b);
    float ac = edge_alpha0(si_c, sj_c);
    float ad = edge_alpha0(si_d, sj_d);

    atomicAdd(g_wd + d4.x, (double)aa + 1048576.0);
    atomicAdd(g_wd + d4.y, (double)ab + 1048576.0);
    atomicAdd(g_wd + d4.z, (double)ac + 1048576.0);
    atomicAdd(g_wd + d4.w, (double)ad + 1048576.0);
}

// ---------------- Kernel 3: out = 0.5*(xh0*w0 + xh1*w1), 8 cols/thread -------
__global__ void out_kernel(float* __restrict__ out, int N)
{
    int i = blockIdx.x * blockDim.x + threadIdx.x;   // over N*8 items
    if (i >= N * 8) return;
    int n  = i >> 3;
    int d8 = (i & 7) << 3;

    float4 ss = *(const float4*)(g_s + 4 * n);
    float aself = edge_alpha0(make_float2(ss.x, ss.y), make_float2(ss.z, ss.w));

    double v   = g_wd[n];
    double deg = floor(v * 9.5367431640625e-07);       // v / 2^20
    float  w0  = (float)(v - deg * 1048576.0) + aself;
    float  w1  = ((float)deg + 1.0f) - w0;

    const __half* xr = g_xh + (size_t)n * 128;
    uint4 ap = *(const uint4*)(xr + d8);        // 8 fp16: head0 cols
    uint4 bp = *(const uint4*)(xr + 64 + d8);   // 8 fp16: head1 cols

    const uint32_t* au = (const uint32_t*)&ap;
    const uint32_t* bu = (const uint32_t*)&bp;
    float o[8];
#pragma unroll
    for (int k = 0; k < 4; k++) {
        float2 a2 = __half22float2(*(const __half2*)&au[k]);
        float2 b2 = __half22float2(*(const __half2*)&bu[k]);
        o[k * 2 + 0] = 0.5f * (a2.x * w0 + b2.x * w1);
        o[k * 2 + 1] = 0.5f * (a2.y * w0 + b2.y * w1);
    }
    *(float4*)(out + (size_t)n * 64 + d8)     = make_float4(o[0], o[1], o[2], o[3]);
    *(float4*)(out + (size_t)n * 64 + d8 + 4) = make_float4(o[4], o[5], o[6], o[7]);
}

// ---------------- launcher ---------------------------------------------------
extern "C" void kernel_launch(void* const* d_in, const int* in_sizes, int n_in,
                              void* d_out, int out_size)
{
    const float* x    = (const float*)d_in[0];
    const float* emb  = (const float*)d_in[1];
    const float* W    = (const float*)d_in[2];
    const float* ai   = (const float*)d_in[3];
    const float* aj   = (const float*)d_in[4];
    const float* aei  = (const float*)d_in[5];
    const float* aej  = (const float*)d_in[6];
    const int*   esrc = (const int*)d_in[7];
    const int*   edst = (const int*)d_in[8];
    float* out = (float*)d_out;

    const int N = in_sizes[0] / 128;   // 50000
    const int E = in_sizes[7];         // 1600000 (divisible by 4)
    const int ntiles = (N + 63) / 64;  // 782
    int grid = 444;                    // 3 CTAs/SM x 148 SMs
    if (grid > ntiles) grid = ntiles;

    cudaFuncSetAttribute(fused_gemm_kernel,
                         cudaFuncAttributeMaxDynamicSharedMemorySize, SMEM_TOTAL);

    const int embBlocks = (N + 7) / 8;                 // 6250
    prep_kernel<<<PREP_WBLK + PREP_XBLK + embBlocks, 256>>>(x, W, emb, aei, aej, N);
    fused_gemm_kernel<<<grid, 256, SMEM_TOTAL>>>(ai, aj, N, ntiles);
    const int Eq = E / 4;
    edge_kernel<<<(Eq + 255) / 256, 256>>>(esrc, edst, Eq);
    out_kernel<<<(N * 8 + 255) / 256, 256>>>(out, N);
}

// round 16
// speedup vs baseline: 1.0281x; 1.0281x over previous
#include <cuda_runtime.h>
#include <cuda_fp16.h>
#include <cstdint>
#include <math.h>

// ---------------- scratch (device globals; no allocations allowed) ----------
#define NMAX 50000
__device__ __half g_xh [(size_t)NMAX * 128]; // xh output, fp16
__device__ __half g_wh [128 * 128];          // W fp16, natural [k][n]
__device__ float  g_s  [NMAX * 4];           // (si0, si1, sj0, sj1) per node
__device__ double g_wd [NMAX];               // packed: deg*2^20 + sum(alpha0)

// ---------------- PTX helpers (base sm_103 target) --------------------------
__device__ __forceinline__ uint32_t smem_u32(const void* p) {
    uint32_t a;
    asm("{ .reg .u64 t; cvta.to.shared.u64 t, %1; cvt.u32.u64 %0, t; }"
        : "=r"(a) : "l"(p));
    return a;
}
__device__ __forceinline__ void ldsm_x4(uint32_t& r0, uint32_t& r1,
                                        uint32_t& r2, uint32_t& r3, uint32_t addr) {
    asm volatile("ldmatrix.sync.aligned.m8n8.x4.shared.b16 {%0,%1,%2,%3}, [%4];"
                 : "=r"(r0), "=r"(r1), "=r"(r2), "=r"(r3) : "r"(addr));
}
__device__ __forceinline__ void ldsm_x4t(uint32_t& r0, uint32_t& r1,
                                         uint32_t& r2, uint32_t& r3, uint32_t addr) {
    asm volatile("ldmatrix.sync.aligned.m8n8.x4.trans.shared.b16 {%0,%1,%2,%3}, [%4];"
                 : "=r"(r0), "=r"(r1), "=r"(r2), "=r"(r3) : "r"(addr));
}
__device__ __forceinline__ void mma16816h(float* c, const uint32_t* a, const uint32_t* b) {
    asm volatile(
        "mma.sync.aligned.m16n8k16.row.col.f32.f16.f16.f32 "
        "{%0,%1,%2,%3}, {%4,%5,%6,%7}, {%8,%9}, {%0,%1,%2,%3};"
        : "+f"(c[0]), "+f"(c[1]), "+f"(c[2]), "+f"(c[3])
        : "r"(a[0]), "r"(a[1]), "r"(a[2]), "r"(a[3]), "r"(b[0]), "r"(b[1]));
}
__device__ __forceinline__ void cpa16(uint32_t dst, const void* src) {
    asm volatile("cp.async.cg.shared.global [%0], [%1], 16;" :: "r"(dst), "l"(src));
}
__device__ __forceinline__ void cpa_commit() {
    asm volatile("cp.async.commit_group;");
}
__device__ __forceinline__ void cpa_wait0() {
    asm volatile("cp.async.wait_group 0;" ::: "memory");
}

__device__ __forceinline__ uint32_t packf2(float a, float b) {
    __half2 h = __float22half2_rn(make_float2(a, b));
    return *(uint32_t*)&h;
}
__device__ __forceinline__ uint2 cvt4h(float4 v) {
    uint2 r;
    r.x = packf2(v.x, v.y);
    r.y = packf2(v.z, v.w);
    return r;
}

// ---------------- SMEM layout (bytes) ----------------------------------------
#define KP 136
#define O_ATT   0                       // 256 floats (ai|aj) = 1024B
#define O_PSI   1024                    // [4 grp][32 rows] = 512B
#define O_PSJ   1536                    // 512B
#define O_A32   2048                    // A staging [32 m][128 k] fp32 = 16384B
#define O_A16   (O_A32 + 16384)         // A tile [32 m][KP k] fp16 = 8704B
#define O_B     (O_A16 + 8704)          // B [128 k][KP n] fp16 = 34816B
#define SMEM_TOTAL (O_B + 34816)        // 61952 -> 3 CTAs/SM

// ---------------- Kernel 0: prep — W->fp16, emb score terms ------------------
#define PREP_WBLK 16
__global__ void prep_kernel(const float* __restrict__ W,
                            const float* __restrict__ emb,
                            const float* __restrict__ aei, const float* __restrict__ aej,
                            int N)
{
    int b = blockIdx.x, tid = threadIdx.x;
    if (b < PREP_WBLK) {                       // W convert: 4096 float4s
        int i = b * 256 + tid;
        ((uint2*)g_wh)[i] = cvt4h(((const float4*)W)[i]);
    } else {                                   // emb score terms: warp per node
        int n = (b - PREP_WBLK) * 8 + (tid >> 5);
        int lane = tid & 31;
        if (n >= N) return;
        float e0 = emb[(size_t)n * 64 + lane];
        float e1 = emb[(size_t)n * 64 + lane + 32];
        float ei0 = e0 * __ldg(aei + lane)      + e1 * __ldg(aei + lane + 32);
        float ei1 = e0 * __ldg(aei + 64 + lane) + e1 * __ldg(aei + 96 + lane);
        float ej0 = e0 * __ldg(aej + lane)      + e1 * __ldg(aej + lane + 32);
        float ej1 = e0 * __ldg(aej + 64 + lane) + e1 * __ldg(aej + 96 + lane);
#pragma unroll
        for (int o = 16; o > 0; o >>= 1) {
            ei0 += __shfl_xor_sync(0xffffffffu, ei0, o);
            ei1 += __shfl_xor_sync(0xffffffffu, ei1, o);
            ej0 += __shfl_xor_sync(0xffffffffu, ej0, o);
            ej1 += __shfl_xor_sync(0xffffffffu, ej1, o);
        }
        if (lane == 0) {
            *(float4*)(g_s + 4 * n) = make_float4(ei0, ei1, ej0, ej1);
            g_wd[n] = 0.0;
        }
    }
}

// ---------------- Kernel 1: persistent GEMM + scores -------------------------
// 32-row x 128-col tile, 256 threads; A loaded fp32 via cp.async, converted in SMEM
__global__ __launch_bounds__(256, 3)
void fused_gemm_kernel(const float* __restrict__ x,
                       const float* __restrict__ ai, const float* __restrict__ aj,
                       int N, int ntiles)
{
    extern __shared__ char sm[];
    const uint32_t smb = smem_u32(sm);
    const int tid = threadIdx.x;
    const int wid = tid >> 5;
    const int lid = tid & 31;

    // issue cp.async for first tile's fp32 A rows (overlaps B staging)
    {
        int row0 = blockIdx.x * 32;
#pragma unroll
        for (int i = 0; i < 4; i++) {
            int idx = tid + i * 256;           // 1024 16B chunks: 32 rows x 32
            int r = idx >> 5, c = (idx & 31) * 4;
            if (row0 + r < N)
                cpa16(smb + O_A32 + (uint32_t)idx * 16,
                      x + (size_t)(row0 + r) * 128 + c);
        }
        cpa_commit();
    }

    // ---- stage B: pure uint4 copy of precomputed fp16 W -----------------------
#pragma unroll
    for (int i = 0; i < 8; i++) {
        int idx = tid + i * 256;
        int k = idx >> 4, n = (idx & 15) * 8;
        *(uint4*)(sm + O_B + (uint32_t)(k * KP + n) * 2) = ((const uint4*)g_wh)[idx];
    }
    // ---- stage attention vectors (ai | aj) -------------------------------------
    {
        float* satt = (float*)(sm + O_ATT);
        satt[tid] = (tid < 128) ? ai[tid] : aj[tid - 128];
    }

    // warp tile: 16 rows x 32 cols
    const int mrow = (wid & 1) * 16;
    const int ncol = (wid >> 1) * 32;
    const int q    = ncol >> 6;
    const int cg   = (ncol >> 5) & 1;
    const int g    = lid >> 2, tig = lid & 3;

    const int l15 = lid & 15;
    const int lh8 = (lid >> 4) * 8;
    const uint32_t aoff = (uint32_t)((mrow + l15) * KP + lh8) * 2;
    const int bkr = ((lid >> 3) & 1) * 8 + (lid & 7);
    const int bnc = (lid >> 4) * 8;
    const uint32_t boff = (uint32_t)(bkr * KP + ncol + bnc) * 2;

    const float* satt = (const float*)(sm + O_ATT);
    const float* attiq = satt + q * 64 + cg * 32;
    const float* attjq = satt + 128 + q * 64 + cg * 32;
    float* psiA = (float*)(sm + O_PSI);
    float* psjA = (float*)(sm + O_PSJ);

    for (int tile = blockIdx.x; tile < ntiles; tile += gridDim.x) {
        const int row0 = tile * 32;

        cpa_wait0();
        __syncthreads();      // A32(t) ready; prior tile fully done (MMA+combine)

        // ---- convert A32 (fp32) -> A16 (fp16, padded) ------------------------------
#pragma unroll
        for (int i = 0; i < 4; i++) {
            int idx = tid + i * 256;           // 1024 float4s
            int r = idx >> 5, c = (idx & 31) * 4;
            float4 v = *(const float4*)(sm + O_A32 + (uint32_t)idx * 16);
            *(uint2*)(sm + O_A16 + (uint32_t)(r * KP + c) * 2) = cvt4h(v);
        }
        __syncthreads();      // A16 visible; A32 free for next tile

        // ---- issue next tile's cp.async (hidden behind MMA + epilogue) -------------
        {
            int nt = tile + gridDim.x;
            if (nt < ntiles) {
                int nrow0 = nt * 32;
#pragma unroll
                for (int i = 0; i < 4; i++) {
                    int idx = tid + i * 256;
                    int r = idx >> 5, c = (idx & 31) * 4;
                    if (nrow0 + r < N)
                        cpa16(smb + O_A32 + (uint32_t)idx * 16,
                              x + (size_t)(nrow0 + r) * 128 + c);
                }
            }
            cpa_commit();
        }

        // ---- MMA: 8 K-steps, warp tile 16x32 ---------------------------------------
        float acc[4][4];
#pragma unroll
        for (int n = 0; n < 4; n++)
#pragma unroll
            for (int k = 0; k < 4; k++) acc[n][k] = 0.f;

#pragma unroll
        for (int ks = 0; ks < 8; ks++) {
            const uint32_t akb = (uint32_t)ks * 32;
            const uint32_t bkb = (uint32_t)ks * (16 * KP * 2);
            uint32_t ah[4], b[4][2];
            ldsm_x4(ah[0], ah[1], ah[2], ah[3], smb + O_A16 + aoff + akb);
#pragma unroll
            for (int p = 0; p < 2; p++)
                ldsm_x4t(b[2 * p][0], b[2 * p][1], b[2 * p + 1][0], b[2 * p + 1][1],
                         smb + O_B + boff + bkb + (uint32_t)p * 32);
#pragma unroll
            for (int n = 0; n < 4; n++) mma16816h(acc[n], ah, b[n]);
        }

        // ---- writeout of xh fragments as fp16 --------------------------------------
#pragma unroll
        for (int n = 0; n < 4; n++) {
            int r = row0 + mrow + g;
            int c = ncol + n * 8 + tig * 2;
            if (r < N)
                *(uint32_t*)(g_xh + (size_t)r * 128 + c) = packf2(acc[n][0], acc[n][1]);
            if (r + 8 < N)
                *(uint32_t*)(g_xh + (size_t)(r + 8) * 128 + c) = packf2(acc[n][2], acc[n][3]);
        }

        // ---- partial scores ----------------------------------------------------------
        float psi[2], psj[2];
#pragma unroll
        for (int h = 0; h < 2; h++) {
            float si = 0.f, sj = 0.f;
#pragma unroll
            for (int n = 0; n < 4; n++) {
                int c = n * 8 + tig * 2;
                float v0 = acc[n][h * 2 + 0];
                float v1 = acc[n][h * 2 + 1];
                si += v0 * attiq[c] + v1 * attiq[c + 1];
                sj += v0 * attjq[c] + v1 * attjq[c + 1];
            }
            psi[h] = si;
            psj[h] = sj;
        }
#pragma unroll
        for (int h = 0; h < 2; h++) {
            psi[h] += __shfl_xor_sync(0xffffffffu, psi[h], 1);
            psi[h] += __shfl_xor_sync(0xffffffffu, psi[h], 2);
            psj[h] += __shfl_xor_sync(0xffffffffu, psj[h], 1);
            psj[h] += __shfl_xor_sync(0xffffffffu, psj[h], 2);
        }
        if (tig == 0) {
#pragma unroll
            for (int h = 0; h < 2; h++) {
                int lrow = mrow + h * 8 + g;
                psiA[(q * 2 + cg) * 32 + lrow] = psi[h];
                psjA[(q * 2 + cg) * 32 + lrow] = psj[h];
            }
        }
        __syncthreads();

        // ---- combine partials, ADD to emb terms already in g_s -----------------------
        if (tid < 32) {
            int grow = row0 + tid;
            if (grow < N) {
                float4 s = *(float4*)(g_s + 4 * grow);
                s.x += psiA[tid]      + psiA[32 + tid];
                s.y += psiA[64 + tid] + psiA[96 + tid];
                s.z += psjA[tid]      + psjA[32 + tid];
                s.w += psjA[64 + tid] + psjA[96 + tid];
                *(float4*)(g_s + 4 * grow) = s;
            }
        }
    }
}

// ---------------- Kernel 2: per-edge attention, 4 edges/thread ---------------
__device__ __forceinline__ float edge_alpha0(float2 si, float2 sj) {
    float a0 = si.x + sj.x;  a0 = fmaxf(a0, 0.2f * a0);
    float a1 = si.y + sj.y;  a1 = fmaxf(a1, 0.2f * a1);
    return __fdividef(1.0f, 1.0f + __expf(a1 - a0));   // = e0/(e0+e1)
}

__global__ void edge_kernel(const int* __restrict__ src, const int* __restrict__ dst,
                            int Eq)
{
    int i = blockIdx.x * blockDim.x + threadIdx.x;
    if (i >= Eq) return;
    int4 s4 = ((const int4*)src)[i];
    int4 d4 = ((const int4*)dst)[i];

    float2 si_a = *(const float2*)(g_s + 4 * s4.x);
    float2 sj_a = *(const float2*)(g_s + 4 * d4.x + 2);
    float2 si_b = *(const float2*)(g_s + 4 * s4.y);
    float2 sj_b = *(const float2*)(g_s + 4 * d4.y + 2);
    float2 si_c = *(const float2*)(g_s + 4 * s4.z);
    float2 sj_c = *(const float2*)(g_s + 4 * d4.z + 2);
    float2 si_d = *(const float2*)(g_s + 4 * s4.w);
    float2 sj_d = *(const float2*)(g_s + 4 * d4.w + 2);

    float aa = edge_alpha0(si_a, sj_a);
    float ab = edge_alpha0(si_b, sj_b);
    float ac = edge_alpha0(si_c, sj_c);
    float ad = edge_alpha0(si_d, sj_d);

    atomicAdd(g_wd + d4.x, (double)aa + 1048576.0);
    atomicAdd(g_wd + d4.y, (double)ab + 1048576.0);
    atomicAdd(g_wd + d4.z, (double)ac + 1048576.0);
    atomicAdd(g_wd + d4.w, (double)ad + 1048576.0);
}

// ---------------- Kernel 3: out = 0.5*(xh0*w0 + xh1*w1), 8 cols/thread -------
__global__ void out_kernel(float* __restrict__ out, int N)
{
    int i = blockIdx.x * blockDim.x + threadIdx.x;   // over N*8 items
    if (i >= N * 8) return;
    int n  = i >> 3;
    int d8 = (i & 7) << 3;

    float4 ss = *(const float4*)(g_s + 4 * n);
    float aself = edge_alpha0(make_float2(ss.x, ss.y), make_float2(ss.z, ss.w));

    double v   = g_wd[n];
    double deg = floor(v * 9.5367431640625e-07);       // v / 2^20
    float  w0  = (float)(v - deg * 1048576.0) + aself;
    float  w1  = ((float)deg + 1.0f) - w0;

    const __half* xr = g_xh + (size_t)n * 128;
    uint4 ap = *(const uint4*)(xr + d8);        // 8 fp16: head0 cols
    uint4 bp = *(const uint4*)(xr + 64 + d8);   // 8 fp16: head1 cols

    const uint32_t* au = (const uint32_t*)&ap;
    const uint32_t* bu = (const uint32_t*)&bp;
    float o[8];
#pragma unroll
    for (int k = 0; k < 4; k++) {
        float2 a2 = __half22float2(*(const __half2*)&au[k]);
        float2 b2 = __half22float2(*(const __half2*)&bu[k]);
        o[k * 2 + 0] = 0.5f * (a2.x * w0 + b2.x * w1);
        o[k * 2 + 1] = 0.5f * (a2.y * w0 + b2.y * w1);
    }
    *(float4*)(out + (size_t)n * 64 + d8)     = make_float4(o[0], o[1], o[2], o[3]);
    *(float4*)(out + (size_t)n * 64 + d8 + 4) = make_float4(o[4], o[5], o[6], o[7]);
}

// ---------------- launcher ---------------------------------------------------
extern "C" void kernel_launch(void* const* d_in, const int* in_sizes, int n_in,
                              void* d_out, int out_size)
{
    const float* x    = (const float*)d_in[0];
    const float* emb  = (const float*)d_in[1];
    const float* W    = (const float*)d_in[2];
    const float* ai   = (const float*)d_in[3];
    const float* aj   = (const float*)d_in[4];
    const float* aei  = (const float*)d_in[5];
    const float* aej  = (const float*)d_in[6];
    const int*   esrc = (const int*)d_in[7];
    const int*   edst = (const int*)d_in[8];
    float* out = (float*)d_out;

    const int N = in_sizes[0] / 128;   // 50000
    const int E = in_sizes[7];         // 1600000 (divisible by 4)
    const int ntiles = (N + 31) / 32;  // 1563
    int grid = 444;                    // 3 CTAs/SM x 148 SMs
    if (grid > ntiles) grid = ntiles;

    cudaFuncSetAttribute(fused_gemm_kernel,
                         cudaFuncAttributeMaxDynamicSharedMemorySize, SMEM_TOTAL);

    const int embBlocks = (N + 7) / 8;                 // 6250
    prep_kernel<<<PREP_WBLK + embBlocks, 256>>>(W, emb, aei, aej, N);
    fused_gemm_kernel<<<grid, 256, SMEM_TOTAL>>>(x, ai, aj, N, ntiles);
    const int Eq = E / 4;
    edge_kernel<<<(Eq + 255) / 256, 256>>>(esrc, edst, Eq);
    out_kernel<<<(N * 8 + 255) / 256, 256>>>(out, N);
}